// round 2
// baseline (speedup 1.0000x reference)
#include <cuda_runtime.h>
#include <cuda_bf16.h>
#include <cstdint>
#include <math.h>

// Problem constants (fixed by the dataset)
#define NMAX 100000
#define EMAX 1600000
#define HDIM 64
#define LMAX 2

// Split-bf16 GEMM: K1 = 3*4*64 = 768 (aggx,x,aggh,h) ; K2 = 3*2*64 = 384 (agg_rh, rh)
#define K1 768
#define K2 384

// ---------------- scratch (static device memory; no allocs allowed) -------
__device__ __align__(16) int   g_deg[NMAX];
__device__ __align__(16) int   g_rowptr[NMAX + 1];
__device__ __align__(16) int   g_cursor[NMAX];
__device__ __align__(16) int   g_csr[EMAX];
__device__ __align__(16) float g_invdeg[NMAX];

__device__ __align__(16) __nv_bfloat16 g_A1[(size_t)NMAX * K1];   // 153.6 MB
__device__ __align__(16) __nv_bfloat16 g_A2[(size_t)NMAX * K2];   // 76.8 MB
__device__ __align__(16) float g_Z [(size_t)NMAX * HDIM];
__device__ __align__(16) float g_TP[(size_t)NMAX * HDIM];
__device__ __align__(16) float g_RH[(size_t)NMAX * HDIM];

__device__ __align__(16) __nv_bfloat16 g_Bt1[(size_t)LMAX * 192 * K1]; // [l][j(192)][k]
__device__ __align__(16) __nv_bfloat16 g_Bt2[(size_t)LMAX * 64 * K2];  // [l][j(64)][k]
__device__ __align__(16) float g_bias1[LMAX * 192];
__device__ __align__(16) float g_bias2[LMAX * 64];

// ---------------- helpers --------------------------------------------------
__device__ __forceinline__ float sigm(float x) { return 1.0f / (1.0f + __expf(-x)); }

__device__ __forceinline__ void split2(float v, __nv_bfloat16& hi, __nv_bfloat16& lo) {
    hi = __float2bfloat16_rn(v);
    lo = __float2bfloat16_rn(v - __bfloat162float(hi));
}

__device__ __forceinline__ void mma_bf16(float (&d)[4], const uint32_t (&a)[4],
                                         const uint32_t (&b)[2]) {
    asm volatile(
        "mma.sync.aligned.m16n8k16.row.col.f32.bf16.bf16.f32 "
        "{%0,%1,%2,%3}, {%4,%5,%6,%7}, {%8,%9}, {%0,%1,%2,%3};\n"
        : "+f"(d[0]), "+f"(d[1]), "+f"(d[2]), "+f"(d[3])
        : "r"(a[0]), "r"(a[1]), "r"(a[2]), "r"(a[3]), "r"(b[0]), "r"(b[1]));
}

// ---------------- CSR build ------------------------------------------------
__global__ void k_zero_deg(int N) {
    int i = blockIdx.x * blockDim.x + threadIdx.x;
    if (i < N) g_deg[i] = 0;
}

// edgidx arrives as int32: [0..E) = src, [E..2E) = dst
__global__ void k_count(const int* __restrict__ edg, int E, int N) {
    int e = blockIdx.x * blockDim.x + threadIdx.x;
    if (e < E) {
        int dst = edg[E + e];
        if ((unsigned)dst < (unsigned)N) atomicAdd(&g_deg[dst], 1);
    }
}

// single-block exclusive scan (N up to NMAX); also writes invdeg + cursor
__global__ void k_scan(int N) {
    __shared__ int wsum[32];
    int tid = threadIdx.x, lane = tid & 31, wid = tid >> 5;
    int carry = 0;
    for (int base = 0; base < N; base += 1024) {
        int i = base + tid;
        int v = (i < N) ? g_deg[i] : 0;
        int x = v;
        #pragma unroll
        for (int o = 1; o < 32; o <<= 1) {
            int y = __shfl_up_sync(0xffffffffu, x, o);
            if (lane >= o) x += y;
        }
        if (lane == 31) wsum[wid] = x;
        __syncthreads();
        if (wid == 0) {
            int w = wsum[lane];
            #pragma unroll
            for (int o = 1; o < 32; o <<= 1) {
                int y = __shfl_up_sync(0xffffffffu, w, o);
                if (lane >= o) w += y;
            }
            wsum[lane] = w;
        }
        __syncthreads();
        int excl = x - v + (wid > 0 ? wsum[wid - 1] : 0) + carry;
        if (i < N) {
            g_rowptr[i] = excl;
            g_cursor[i] = excl;
            g_invdeg[i] = (v > 0) ? 1.0f / (float)v : 0.0f;
        }
        carry += wsum[31];
        __syncthreads();
    }
    if (tid == 0) g_rowptr[N] = carry;
}

__global__ void k_scatter(const int* __restrict__ edg, int E, int N) {
    int e = blockIdx.x * blockDim.x + threadIdx.x;
    if (e < E) {
        int src = edg[e];
        int dst = edg[E + e];
        if ((unsigned)src < (unsigned)N && (unsigned)dst < (unsigned)N) {
            int pos = atomicAdd(&g_cursor[dst], 1);
            g_csr[pos] = src;
        }
    }
}

// ---------------- weight / bias packing ------------------------------------
// Bt1[l][j][k], j = g*64+jj (g: 0=z 1=r 2=t), k = t*256 + s*64 + c
// s: 0=aggx(Wl gate g0) 1=x(Wr g0) 2=aggh(Wl g1) 3=h(Wr g1); g0={0,2,4}, g1={1,3,-}
// t: 0 -> hi(w) (pairs A_hi), 1 -> hi(w) (pairs A_lo), 2 -> lo(w) (pairs A_hi)
__global__ void k_packB1(const float* __restrict__ Wl, const float* __restrict__ Wr, int L) {
    int idx = blockIdx.x * blockDim.x + threadIdx.x;
    int total = L * 192 * K1;
    if (idx >= total) return;
    int k = idx % K1;
    int j = (idx / K1) % 192;
    int l = idx / (K1 * 192);
    int t = k / 256, rem = k % 256, s = rem / 64, c = rem % 64;
    int g = j / 64, jj = j % 64;
    int gbase = 2 * g;
    float w = 0.0f;
    if (s == 0)      w = Wl[(((size_t)l * 6 + gbase) * 64 + jj) * 64 + c];
    else if (s == 1) w = Wr[(((size_t)l * 6 + gbase) * 64 + jj) * 64 + c];
    else if (s == 2) { if (g < 2) w = Wl[(((size_t)l * 6 + gbase + 1) * 64 + jj) * 64 + c]; }
    else             { if (g < 2) w = Wr[(((size_t)l * 6 + gbase + 1) * 64 + jj) * 64 + c]; }
    __nv_bfloat16 hi = __float2bfloat16_rn(w);
    __nv_bfloat16 val = (t == 2) ? __float2bfloat16_rn(w - __bfloat162float(hi)) : hi;
    g_Bt1[(size_t)(l * 192 + j) * K1 + k] = val;
}

// Bt2[l][j][k], k = t*128 + s*64 + c ; s: 0=agg_rh(Wl5), 1=rh(Wr5)
__global__ void k_packB2(const float* __restrict__ Wl, const float* __restrict__ Wr, int L) {
    int idx = blockIdx.x * blockDim.x + threadIdx.x;
    int total = L * 64 * K2;
    if (idx >= total) return;
    int k = idx % K2;
    int j = (idx / K2) % 64;
    int l = idx / (K2 * 64);
    int t = k / 128, rem = k % 128, s = rem / 64, c = rem % 64;
    const float* W = s ? Wr : Wl;
    float w = W[(((size_t)l * 6 + 5) * 64 + j) * 64 + c];
    __nv_bfloat16 hi = __float2bfloat16_rn(w);
    __nv_bfloat16 val = (t == 2) ? __float2bfloat16_rn(w - __bfloat162float(hi)) : hi;
    g_Bt2[(size_t)(l * 64 + j) * K2 + k] = val;
}

__global__ void k_packBias(const float* __restrict__ b, int L) {
    int idx = blockIdx.x * blockDim.x + threadIdx.x;
    int total = L * 256;
    if (idx >= total) return;
    int j = idx % 256, l = idx / 256;
    if (j < 192) {
        int g = j / 64, jj = j % 64;
        float v;
        if (g == 0)      v = b[((size_t)l * 6 + 0) * 64 + jj] + b[((size_t)l * 6 + 1) * 64 + jj];
        else if (g == 1) v = b[((size_t)l * 6 + 2) * 64 + jj] + b[((size_t)l * 6 + 3) * 64 + jj];
        else             v = b[((size_t)l * 6 + 4) * 64 + jj];
        g_bias1[l * 192 + j] = v;
    } else {
        int jj = j - 192;
        g_bias2[l * 64 + jj] = b[((size_t)l * 6 + 5) * 64 + jj];
    }
}

// ---------------- aggregation (warp per node, CSR gather) ------------------
__device__ __forceinline__ void pack_src1(__nv_bfloat16* A, int s, int c, float v) {
    __nv_bfloat16 hi, lo; split2(v, hi, lo);
    A[s * 64 + c]       = hi;
    A[256 + s * 64 + c] = lo;
    A[512 + s * 64 + c] = hi;
}

__global__ void k_agg1(const float* __restrict__ x, const float* __restrict__ h, int N) {
    int warp = (blockIdx.x * blockDim.x + threadIdx.x) >> 5;
    if (warp >= N) return;
    int lane = threadIdx.x & 31;
    int beg = g_rowptr[warp], end = g_rowptr[warp + 1];
    float sx0 = 0.f, sx1 = 0.f, sh0 = 0.f, sh1 = 0.f;
    for (int e = beg; e < end; e++) {
        int s = g_csr[e];
        const float* xr = x + (size_t)s * HDIM;
        const float* hr = h + (size_t)s * HDIM;
        sx0 += xr[lane];      sx1 += xr[lane + 32];
        sh0 += hr[lane];      sh1 += hr[lane + 32];
    }
    float inv = g_invdeg[warp];
    sx0 *= inv; sx1 *= inv; sh0 *= inv; sh1 *= inv;
    const float* xr = x + (size_t)warp * HDIM;
    const float* hr = h + (size_t)warp * HDIM;
    float xv0 = xr[lane], xv1 = xr[lane + 32];
    float hv0 = hr[lane], hv1 = hr[lane + 32];
    __nv_bfloat16* A = g_A1 + (size_t)warp * K1;
    pack_src1(A, 0, lane, sx0);  pack_src1(A, 0, lane + 32, sx1);
    pack_src1(A, 1, lane, xv0);  pack_src1(A, 1, lane + 32, xv1);
    pack_src1(A, 2, lane, sh0);  pack_src1(A, 2, lane + 32, sh1);
    pack_src1(A, 3, lane, hv0);  pack_src1(A, 3, lane + 32, hv1);
}

__global__ void k_agg2(int N) {
    int warp = (blockIdx.x * blockDim.x + threadIdx.x) >> 5;
    if (warp >= N) return;
    int lane = threadIdx.x & 31;
    int beg = g_rowptr[warp], end = g_rowptr[warp + 1];
    float s0 = 0.f, s1 = 0.f;
    for (int e = beg; e < end; e++) {
        const float* rr = g_RH + (size_t)g_csr[e] * HDIM;
        s0 += rr[lane];
        s1 += rr[lane + 32];
    }
    float inv = g_invdeg[warp];
    s0 *= inv; s1 *= inv;
    __nv_bfloat16* A = g_A2 + (size_t)warp * K2;
    {
        __nv_bfloat16 hi, lo; split2(s0, hi, lo);
        A[lane] = hi; A[128 + lane] = lo; A[256 + lane] = hi;
    }
    {
        __nv_bfloat16 hi, lo; split2(s1, hi, lo);
        A[lane + 32] = hi; A[128 + lane + 32] = lo; A[256 + lane + 32] = hi;
    }
}

// ---------------- GEMMs (split-bf16 via mma.sync m16n8k16) -----------------
// block: 256 threads (8 warps, 4x2 warp grid), tile BM=128 x BN=64, BK=64
#define BM 128
#define BKC 64
#define SMPAD 72   // bf16 row stride in smem (64 data + 8 pad, 16B aligned)

__global__ void __launch_bounds__(256) k_gemm1(int N, int l, const float* __restrict__ hptr) {
    __shared__ __align__(16) __nv_bfloat16 As[BM][SMPAD];
    __shared__ __align__(16) __nv_bfloat16 Bs[64][SMPAD];
    int n0 = blockIdx.x * BM;
    int g  = blockIdx.y;          // 0=z, 1=r, 2=t-partial
    int tid = threadIdx.x;
    int wid = tid >> 5, lane = tid & 31;
    int warpM = wid >> 1, warpN = wid & 1;
    float acc[2][4][4];
    #pragma unroll
    for (int a = 0; a < 2; a++)
        #pragma unroll
        for (int bq = 0; bq < 4; bq++)
            #pragma unroll
            for (int c = 0; c < 4; c++) acc[a][bq][c] = 0.f;

    const __nv_bfloat16* Bg = g_Bt1 + (size_t)(l * 192 + g * 64) * K1;

    for (int kc = 0; kc < K1 / BKC; kc++) {
        #pragma unroll
        for (int i = 0; i < 4; i++) {
            int idx = tid + i * 256;
            int r = idx >> 3, c8 = idx & 7;
            int4 v = make_int4(0, 0, 0, 0);
            if (n0 + r < N)
                v = *(const int4*)(g_A1 + (size_t)(n0 + r) * K1 + kc * BKC + c8 * 8);
            *(int4*)&As[r][c8 * 8] = v;
        }
        #pragma unroll
        for (int i = 0; i < 2; i++) {
            int idx = tid + i * 256;
            int j = idx >> 3, c8 = idx & 7;
            *(int4*)&Bs[j][c8 * 8] =
                *(const int4*)(Bg + (size_t)j * K1 + kc * BKC + c8 * 8);
        }
        __syncthreads();
        #pragma unroll
        for (int ks = 0; ks < 4; ks++) {
            int cc = ks * 16 + (lane & 3) * 2;
            uint32_t a[2][4], b[4][2];
            #pragma unroll
            for (int mt = 0; mt < 2; mt++) {
                int r = warpM * 32 + mt * 16 + (lane >> 2);
                a[mt][0] = *(const uint32_t*)&As[r][cc];
                a[mt][1] = *(const uint32_t*)&As[r + 8][cc];
                a[mt][2] = *(const uint32_t*)&As[r][cc + 8];
                a[mt][3] = *(const uint32_t*)&As[r + 8][cc + 8];
            }
            #pragma unroll
            for (int nt = 0; nt < 4; nt++) {
                int cl = warpN * 32 + nt * 8 + (lane >> 2);
                b[nt][0] = *(const uint32_t*)&Bs[cl][cc];
                b[nt][1] = *(const uint32_t*)&Bs[cl][cc + 8];
            }
            #pragma unroll
            for (int mt = 0; mt < 2; mt++)
                #pragma unroll
                for (int nt = 0; nt < 4; nt++)
                    mma_bf16(acc[mt][nt], a[mt], b[nt]);
        }
        __syncthreads();
    }

    // epilogue
    #pragma unroll
    for (int mt = 0; mt < 2; mt++) {
        #pragma unroll
        for (int nt = 0; nt < 4; nt++) {
            int r0  = n0 + warpM * 32 + mt * 16 + (lane >> 2);
            int jc0 = warpN * 32 + nt * 8 + (lane & 3) * 2;
            #pragma unroll
            for (int q = 0; q < 4; q++) {
                int row = (q < 2) ? r0 : r0 + 8;
                int jc  = jc0 + (q & 1);
                float val = acc[mt][nt][q];
                if (row < N) {
                    float v = val + g_bias1[l * 192 + g * 64 + jc];
                    size_t o = (size_t)row * HDIM + jc;
                    if (g == 0) {
                        g_Z[o] = sigm(v);
                    } else if (g == 1) {
                        float r = sigm(v);
                        float rh = r * hptr[o];
                        g_RH[o] = rh;
                        __nv_bfloat16 hi, lo; split2(rh, hi, lo);
                        size_t base = (size_t)row * K2;
                        g_A2[base + 64 + jc]  = hi;
                        g_A2[base + 192 + jc] = lo;
                        g_A2[base + 320 + jc] = hi;
                    } else {
                        g_TP[o] = v;
                    }
                }
            }
        }
    }
}

__global__ void __launch_bounds__(256) k_gemm2(int N, int l,
                                               const float* __restrict__ hptr,
                                               float* __restrict__ out) {
    __shared__ __align__(16) __nv_bfloat16 As[BM][SMPAD];
    __shared__ __align__(16) __nv_bfloat16 Bs[64][SMPAD];
    int n0 = blockIdx.x * BM;
    int tid = threadIdx.x;
    int wid = tid >> 5, lane = tid & 31;
    int warpM = wid >> 1, warpN = wid & 1;
    float acc[2][4][4];
    #pragma unroll
    for (int a = 0; a < 2; a++)
        #pragma unroll
        for (int bq = 0; bq < 4; bq++)
            #pragma unroll
            for (int c = 0; c < 4; c++) acc[a][bq][c] = 0.f;

    const __nv_bfloat16* Bg = g_Bt2 + (size_t)(l * 64) * K2;

    for (int kc = 0; kc < K2 / BKC; kc++) {
        #pragma unroll
        for (int i = 0; i < 4; i++) {
            int idx = tid + i * 256;
            int r = idx >> 3, c8 = idx & 7;
            int4 v = make_int4(0, 0, 0, 0);
            if (n0 + r < N)
                v = *(const int4*)(g_A2 + (size_t)(n0 + r) * K2 + kc * BKC + c8 * 8);
            *(int4*)&As[r][c8 * 8] = v;
        }
        #pragma unroll
        for (int i = 0; i < 2; i++) {
            int idx = tid + i * 256;
            int j = idx >> 3, c8 = idx & 7;
            *(int4*)&Bs[j][c8 * 8] =
                *(const int4*)(Bg + (size_t)j * K2 + kc * BKC + c8 * 8);
        }
        __syncthreads();
        #pragma unroll
        for (int ks = 0; ks < 4; ks++) {
            int cc = ks * 16 + (lane & 3) * 2;
            uint32_t a[2][4], b[4][2];
            #pragma unroll
            for (int mt = 0; mt < 2; mt++) {
                int r = warpM * 32 + mt * 16 + (lane >> 2);
                a[mt][0] = *(const uint32_t*)&As[r][cc];
                a[mt][1] = *(const uint32_t*)&As[r + 8][cc];
                a[mt][2] = *(const uint32_t*)&As[r][cc + 8];
                a[mt][3] = *(const uint32_t*)&As[r + 8][cc + 8];
            }
            #pragma unroll
            for (int nt = 0; nt < 4; nt++) {
                int cl = warpN * 32 + nt * 8 + (lane >> 2);
                b[nt][0] = *(const uint32_t*)&Bs[cl][cc];
                b[nt][1] = *(const uint32_t*)&Bs[cl][cc + 8];
            }
            #pragma unroll
            for (int mt = 0; mt < 2; mt++)
                #pragma unroll
                for (int nt = 0; nt < 4; nt++)
                    mma_bf16(acc[mt][nt], a[mt], b[nt]);
        }
        __syncthreads();
    }

    #pragma unroll
    for (int mt = 0; mt < 2; mt++) {
        #pragma unroll
        for (int nt = 0; nt < 4; nt++) {
            int r0  = n0 + warpM * 32 + mt * 16 + (lane >> 2);
            int jc0 = warpN * 32 + nt * 8 + (lane & 3) * 2;
            #pragma unroll
            for (int q = 0; q < 4; q++) {
                int row = (q < 2) ? r0 : r0 + 8;
                int jc  = jc0 + (q & 1);
                if (row < N) {
                    size_t o = (size_t)row * HDIM + jc;
                    float v = acc[mt][nt][q] + g_bias2[l * 64 + jc] + g_TP[o];
                    float t = tanhf(v);
                    float z = g_Z[o];
                    float hv = hptr[o];
                    out[(size_t)l * N * HDIM + o] = z * hv + (1.0f - z) * t;
                }
            }
        }
    }
}

// ---------------- launch ----------------------------------------------------
extern "C" void kernel_launch(void* const* d_in, const int* in_sizes, int n_in,
                              void* d_out, int out_size) {
    const float* inp = (const float*)d_in[0];
    const int*   edg = (const int*)d_in[1];     // int64 in reference -> int32 in harness
    const float* h   = (const float*)d_in[2];
    const float* Wl  = (const float*)d_in[3];
    const float* b   = (const float*)d_in[4];
    const float* Wr  = (const float*)d_in[5];
    float* out = (float*)d_out;

    int N = in_sizes[0] / HDIM;
    int E = in_sizes[1] / 2;
    int L = in_sizes[2] / in_sizes[0];
    if (N > NMAX || E > EMAX || L > LMAX) return;

    // CSR build
    k_zero_deg<<<(N + 255) / 256, 256>>>(N);
    k_count<<<(E + 255) / 256, 256>>>(edg, E, N);
    k_scan<<<1, 1024>>>(N);
    k_scatter<<<(E + 255) / 256, 256>>>(edg, E, N);

    // weight packing (hi/lo split, transposed + concatenated)
    k_packB1<<<(L * 192 * K1 + 255) / 256, 256>>>(Wl, Wr, L);
    k_packB2<<<(L * 64 * K2 + 255) / 256, 256>>>(Wl, Wr, L);
    k_packBias<<<(L * 256 + 255) / 256, 256>>>(b, L);

    int aggBlocks  = (N * 32 + 255) / 256;
    int rowTiles   = (N + BM - 1) / BM;

    const float* x = inp;
    for (int l = 0; l < L; l++) {
        const float* hl = h + (size_t)l * N * HDIM;
        k_agg1<<<aggBlocks, 256>>>(x, hl, N);
        dim3 grid1(rowTiles, 3);
        k_gemm1<<<grid1, 256>>>(N, l, hl);
        k_agg2<<<aggBlocks, 256>>>(N);
        k_gemm2<<<rowTiles, 256>>>(N, l, hl, out);
        x = out + (size_t)l * N * HDIM;
    }
}

// round 3
// speedup vs baseline: 1.1143x; 1.1143x over previous
#include <cuda_runtime.h>
#include <cuda_bf16.h>
#include <cstdint>
#include <math.h>

// Problem constants (fixed by the dataset)
#define NMAX 100000
#define EMAX 1600000
#define HDIM 64
#define LMAX 2

// Dedup split-bf16 layouts:
// A1 row: [hi(4x64) | lo(4x64)]  K1A=512 ; B1 row: [hi(4x64) | lo(4x64)] K1B=512
// A2 row: [hi_agg(64) hi_rh(64) | lo_agg(64) lo_rh(64)] K2A=256 ; B2 same idea K2B=256
#define K1A 512
#define K1B 512
#define K2A 256
#define K2B 256

// ---------------- scratch (static device memory; no allocs allowed) -------
__device__ __align__(16) int   g_deg[NMAX];
__device__ __align__(16) int   g_rowptr[NMAX + 1];
__device__ __align__(16) int   g_cursor[NMAX];
__device__ __align__(16) int   g_csr[EMAX];
__device__ __align__(16) float g_invdeg[NMAX];

__device__ __align__(16) __nv_bfloat16 g_A1[(size_t)NMAX * K1A];   // 102.4 MB
__device__ __align__(16) __nv_bfloat16 g_A2[(size_t)NMAX * K2A];   // 51.2 MB
__device__ __align__(16) float g_Z [(size_t)NMAX * HDIM];
__device__ __align__(16) float g_TP[(size_t)NMAX * HDIM];
__device__ __align__(16) float g_RH[(size_t)NMAX * HDIM];

__device__ __align__(16) __nv_bfloat16 g_Bt1[(size_t)LMAX * 192 * K1B];
__device__ __align__(16) __nv_bfloat16 g_Bt2[(size_t)LMAX * 64 * K2B];
__device__ __align__(16) float g_bias1[LMAX * 192];
__device__ __align__(16) float g_bias2[LMAX * 64];

// ---------------- helpers --------------------------------------------------
__device__ __forceinline__ float sigm(float x) { return 1.0f / (1.0f + __expf(-x)); }

__device__ __forceinline__ void split2(float v, __nv_bfloat16& hi, __nv_bfloat16& lo) {
    hi = __float2bfloat16_rn(v);
    lo = __float2bfloat16_rn(v - __bfloat162float(hi));
}

__device__ __forceinline__ void mma_bf16(float (&d)[4], const uint32_t (&a)[4],
                                         const uint32_t (&b)[2]) {
    asm volatile(
        "mma.sync.aligned.m16n8k16.row.col.f32.bf16.bf16.f32 "
        "{%0,%1,%2,%3}, {%4,%5,%6,%7}, {%8,%9}, {%0,%1,%2,%3};\n"
        : "+f"(d[0]), "+f"(d[1]), "+f"(d[2]), "+f"(d[3])
        : "r"(a[0]), "r"(a[1]), "r"(a[2]), "r"(a[3]), "r"(b[0]), "r"(b[1]));
}

__device__ __forceinline__ uint32_t sptr(const void* p) {
    return (uint32_t)__cvta_generic_to_shared(p);
}

__device__ __forceinline__ void ldsm_x4(uint32_t (&r)[4], uint32_t addr) {
    asm volatile("ldmatrix.sync.aligned.m8n8.x4.shared.b16 {%0,%1,%2,%3}, [%4];\n"
                 : "=r"(r[0]), "=r"(r[1]), "=r"(r[2]), "=r"(r[3]) : "r"(addr));
}

// ---------------- CSR build ------------------------------------------------
__global__ void k_zero_deg(int N) {
    int i = blockIdx.x * blockDim.x + threadIdx.x;
    if (i < N) g_deg[i] = 0;
}

// edgidx arrives as int32: [0..E) = src, [E..2E) = dst
__global__ void k_count(const int* __restrict__ edg, int E, int N) {
    int e = blockIdx.x * blockDim.x + threadIdx.x;
    if (e < E) {
        int dst = edg[E + e];
        if ((unsigned)dst < (unsigned)N) atomicAdd(&g_deg[dst], 1);
    }
}

__global__ void k_scan(int N) {
    __shared__ int wsum[32];
    int tid = threadIdx.x, lane = tid & 31, wid = tid >> 5;
    int carry = 0;
    for (int base = 0; base < N; base += 1024) {
        int i = base + tid;
        int v = (i < N) ? g_deg[i] : 0;
        int x = v;
        #pragma unroll
        for (int o = 1; o < 32; o <<= 1) {
            int y = __shfl_up_sync(0xffffffffu, x, o);
            if (lane >= o) x += y;
        }
        if (lane == 31) wsum[wid] = x;
        __syncthreads();
        if (wid == 0) {
            int w = wsum[lane];
            #pragma unroll
            for (int o = 1; o < 32; o <<= 1) {
                int y = __shfl_up_sync(0xffffffffu, w, o);
                if (lane >= o) w += y;
            }
            wsum[lane] = w;
        }
        __syncthreads();
        int excl = x - v + (wid > 0 ? wsum[wid - 1] : 0) + carry;
        if (i < N) {
            g_rowptr[i] = excl;
            g_cursor[i] = excl;
            g_invdeg[i] = (v > 0) ? 1.0f / (float)v : 0.0f;
        }
        carry += wsum[31];
        __syncthreads();
    }
    if (tid == 0) g_rowptr[N] = carry;
}

__global__ void k_scatter(const int* __restrict__ edg, int E, int N) {
    int e = blockIdx.x * blockDim.x + threadIdx.x;
    if (e < E) {
        int src = edg[e];
        int dst = edg[E + e];
        if ((unsigned)src < (unsigned)N && (unsigned)dst < (unsigned)N) {
            int pos = atomicAdd(&g_cursor[dst], 1);
            g_csr[pos] = src;
        }
    }
}

// ---------------- weight / bias packing ------------------------------------
// B1[l][j][k]: j = g*64+jj (g: 0=z 1=r 2=t-partial), k = t*256 + s*64 + c
// s: 0=Wl(g0) 1=Wr(g0) 2=Wl(g1) 3=Wr(g1), gate pairs (0,1),(2,3),(4,-)
// t: 0 -> hi(w), 1 -> lo(w)
__global__ void k_packB1(const float* __restrict__ Wl, const float* __restrict__ Wr, int L) {
    int idx = blockIdx.x * blockDim.x + threadIdx.x;
    int total = L * 192 * K1B;
    if (idx >= total) return;
    int k = idx % K1B;
    int j = (idx / K1B) % 192;
    int l = idx / (K1B * 192);
    int t = k / 256, rem = k % 256, s = rem / 64, c = rem % 64;
    int g = j / 64, jj = j % 64;
    int gbase = 2 * g;
    float w = 0.0f;
    if (s == 0)      w = Wl[(((size_t)l * 6 + gbase) * 64 + jj) * 64 + c];
    else if (s == 1) w = Wr[(((size_t)l * 6 + gbase) * 64 + jj) * 64 + c];
    else if (s == 2) { if (g < 2) w = Wl[(((size_t)l * 6 + gbase + 1) * 64 + jj) * 64 + c]; }
    else             { if (g < 2) w = Wr[(((size_t)l * 6 + gbase + 1) * 64 + jj) * 64 + c]; }
    __nv_bfloat16 hi = __float2bfloat16_rn(w);
    __nv_bfloat16 val = (t == 1) ? __float2bfloat16_rn(w - __bfloat162float(hi)) : hi;
    g_Bt1[(size_t)(l * 192 + j) * K1B + k] = val;
}

// B2[l][j][k]: k = t*128 + s*64 + c ; s: 0=Wl5(agg_rh) 1=Wr5(rh); t: 0=hi 1=lo
__global__ void k_packB2(const float* __restrict__ Wl, const float* __restrict__ Wr, int L) {
    int idx = blockIdx.x * blockDim.x + threadIdx.x;
    int total = L * 64 * K2B;
    if (idx >= total) return;
    int k = idx % K2B;
    int j = (idx / K2B) % 64;
    int l = idx / (K2B * 64);
    int t = k / 128, rem = k % 128, s = rem / 64, c = rem % 64;
    const float* W = s ? Wr : Wl;
    float w = W[(((size_t)l * 6 + 5) * 64 + j) * 64 + c];
    __nv_bfloat16 hi = __float2bfloat16_rn(w);
    __nv_bfloat16 val = (t == 1) ? __float2bfloat16_rn(w - __bfloat162float(hi)) : hi;
    g_Bt2[(size_t)(l * 64 + j) * K2B + k] = val;
}

__global__ void k_packBias(const float* __restrict__ b, int L) {
    int idx = blockIdx.x * blockDim.x + threadIdx.x;
    int total = L * 256;
    if (idx >= total) return;
    int j = idx % 256, l = idx / 256;
    if (j < 192) {
        int g = j / 64, jj = j % 64;
        float v;
        if (g == 0)      v = b[((size_t)l * 6 + 0) * 64 + jj] + b[((size_t)l * 6 + 1) * 64 + jj];
        else if (g == 1) v = b[((size_t)l * 6 + 2) * 64 + jj] + b[((size_t)l * 6 + 3) * 64 + jj];
        else             v = b[((size_t)l * 6 + 4) * 64 + jj];
        g_bias1[l * 192 + j] = v;
    } else {
        int jj = j - 192;
        g_bias2[l * 64 + jj] = b[((size_t)l * 6 + 5) * 64 + jj];
    }
}

// ---------------- aggregation (warp per node, CSR gather) ------------------
__device__ __forceinline__ void pack_src1(__nv_bfloat16* A, int s, int c, float v) {
    __nv_bfloat16 hi, lo; split2(v, hi, lo);
    A[s * 64 + c]       = hi;
    A[256 + s * 64 + c] = lo;
}

__global__ void k_agg1(const float* __restrict__ x, const float* __restrict__ h, int N) {
    int warp = (blockIdx.x * blockDim.x + threadIdx.x) >> 5;
    if (warp >= N) return;
    int lane = threadIdx.x & 31;
    int beg = g_rowptr[warp], end = g_rowptr[warp + 1];
    float sx0 = 0.f, sx1 = 0.f, sh0 = 0.f, sh1 = 0.f;
    for (int e = beg; e < end; e++) {
        int s = g_csr[e];
        const float* xr = x + (size_t)s * HDIM;
        const float* hr = h + (size_t)s * HDIM;
        sx0 += xr[lane];      sx1 += xr[lane + 32];
        sh0 += hr[lane];      sh1 += hr[lane + 32];
    }
    float inv = g_invdeg[warp];
    sx0 *= inv; sx1 *= inv; sh0 *= inv; sh1 *= inv;
    const float* xr = x + (size_t)warp * HDIM;
    const float* hr = h + (size_t)warp * HDIM;
    float xv0 = xr[lane], xv1 = xr[lane + 32];
    float hv0 = hr[lane], hv1 = hr[lane + 32];
    __nv_bfloat16* A = g_A1 + (size_t)warp * K1A;
    pack_src1(A, 0, lane, sx0);  pack_src1(A, 0, lane + 32, sx1);
    pack_src1(A, 1, lane, xv0);  pack_src1(A, 1, lane + 32, xv1);
    pack_src1(A, 2, lane, sh0);  pack_src1(A, 2, lane + 32, sh1);
    pack_src1(A, 3, lane, hv0);  pack_src1(A, 3, lane + 32, hv1);
}

__global__ void k_agg2(int N) {
    int warp = (blockIdx.x * blockDim.x + threadIdx.x) >> 5;
    if (warp >= N) return;
    int lane = threadIdx.x & 31;
    int beg = g_rowptr[warp], end = g_rowptr[warp + 1];
    float s0 = 0.f, s1 = 0.f;
    for (int e = beg; e < end; e++) {
        const float* rr = g_RH + (size_t)g_csr[e] * HDIM;
        s0 += rr[lane];
        s1 += rr[lane + 32];
    }
    float inv = g_invdeg[warp];
    s0 *= inv; s1 *= inv;
    __nv_bfloat16* A = g_A2 + (size_t)warp * K2A;
    {
        __nv_bfloat16 hi, lo; split2(s0, hi, lo);
        A[lane] = hi; A[128 + lane] = lo;          // hi_agg | lo_agg
    }
    {
        __nv_bfloat16 hi, lo; split2(s1, hi, lo);
        A[lane + 32] = hi; A[128 + lane + 32] = lo;
    }
}

// ---------------- GEMM 1: all gates fused, A read once ---------------------
// 512 threads, 16 warps (4M x 4N), BM=128, BN=192, warp tile 32x48
#define BM 128
#define SMPAD 72   // bf16 row stride (144B: 16B aligned, conflict-free ldmatrix)

__global__ void __launch_bounds__(512) k_gemm1(int N, int l, const float* __restrict__ hptr) {
    extern __shared__ __nv_bfloat16 smem1[];
    __nv_bfloat16 (*As)[SMPAD] = (__nv_bfloat16(*)[SMPAD])smem1;
    __nv_bfloat16* BsBase = smem1 + BM * SMPAD;   // 2 buffers of [192][SMPAD]

    int n0 = blockIdx.x * BM;
    int tid = threadIdx.x;
    int wid = tid >> 5, lane = tid & 31;
    int warpM = wid >> 2, warpN = wid & 3;

    float acc[2][6][4];
    #pragma unroll
    for (int mt = 0; mt < 2; mt++)
        #pragma unroll
        for (int nt = 0; nt < 6; nt++)
            #pragma unroll
            for (int q = 0; q < 4; q++) acc[mt][nt][q] = 0.f;

    const __nv_bfloat16* Bg = g_Bt1 + (size_t)l * 192 * K1B;

    for (int kc = 0; kc < 8; kc++) {
        // A chunk (128 x 64)
        #pragma unroll
        for (int i = 0; i < 2; i++) {
            int idx = tid + i * 512;
            int r = idx >> 3, c8 = idx & 7;
            int4 v = make_int4(0, 0, 0, 0);
            if (n0 + r < N)
                v = *(const int4*)(g_A1 + (size_t)(n0 + r) * K1A + kc * 64 + c8 * 8);
            *(int4*)&As[r][c8 * 8] = v;
        }
        int nb = (kc < 4) ? 2 : 1;   // hi A-chunks pair with B_hi and B_lo
        for (int p = 0; p < nb; p++) {
            int bk = (kc < 4) ? (kc + p * 4) : (kc - 4);
            __nv_bfloat16* Bp = BsBase + p * (192 * SMPAD);
            #pragma unroll
            for (int i = 0; i < 3; i++) {
                int idx = tid + i * 512;
                int j = idx >> 3, c8 = idx & 7;
                *(int4*)(Bp + j * SMPAD + c8 * 8) =
                    *(const int4*)(Bg + (size_t)j * K1B + bk * 64 + c8 * 8);
            }
        }
        __syncthreads();
        #pragma unroll
        for (int ks = 0; ks < 4; ks++) {
            int cc = ks * 16;
            uint32_t a[2][4];
            #pragma unroll
            for (int mt = 0; mt < 2; mt++) {
                int row = warpM * 32 + mt * 16 + (lane & 15);
                int col = cc + ((lane >> 4) << 3);
                ldsm_x4(a[mt], sptr(&As[row][col]));
            }
            for (int p = 0; p < nb; p++) {
                const __nv_bfloat16* Bp = BsBase + p * (192 * SMPAD);
                uint32_t b[6][2];
                #pragma unroll
                for (int pr = 0; pr < 3; pr++) {
                    int j = warpN * 48 + pr * 16 + ((lane >> 4) << 3) + (lane & 7);
                    int col = cc + (((lane >> 3) & 1) << 3);
                    uint32_t t4[4];
                    ldsm_x4(t4, sptr(Bp + j * SMPAD + col));
                    b[pr * 2][0] = t4[0]; b[pr * 2][1] = t4[1];
                    b[pr * 2 + 1][0] = t4[2]; b[pr * 2 + 1][1] = t4[3];
                }
                #pragma unroll
                for (int mt = 0; mt < 2; mt++)
                    #pragma unroll
                    for (int nt = 0; nt < 6; nt++)
                        mma_bf16(acc[mt][nt], a[mt], b[nt]);
            }
        }
        __syncthreads();
    }

    // fused epilogue: z | r (+rh pack) | t-partial
    #pragma unroll
    for (int mt = 0; mt < 2; mt++) {
        int r0 = n0 + warpM * 32 + mt * 16 + (lane >> 2);
        #pragma unroll
        for (int nt = 0; nt < 6; nt++) {
            int jc0 = warpN * 48 + nt * 8 + (lane & 3) * 2;
            #pragma unroll
            for (int q = 0; q < 4; q++) {
                int row = r0 + ((q >> 1) << 3);
                int jc  = jc0 + (q & 1);
                if (row < N) {
                    float v = acc[mt][nt][q] + g_bias1[l * 192 + jc];
                    int jj = jc & 63;
                    size_t o = (size_t)row * HDIM + jj;
                    if (jc < 64) {
                        g_Z[o] = sigm(v);
                    } else if (jc < 128) {
                        float r = sigm(v);
                        float rh = r * hptr[o];
                        g_RH[o] = rh;
                        __nv_bfloat16 hi, lo; split2(rh, hi, lo);
                        size_t base = (size_t)row * K2A;
                        g_A2[base + 64 + jj]  = hi;   // hi_rh
                        g_A2[base + 192 + jj] = lo;   // lo_rh
                    } else {
                        g_TP[o] = v;
                    }
                }
            }
        }
    }
}

// ---------------- GEMM 2: gate 5 + final GRU combine -----------------------
// 256 threads, 8 warps (4M x 2N), BM=128, BN=64, warp tile 32x32
__global__ void __launch_bounds__(256) k_gemm2(int N, int l,
                                               const float* __restrict__ hptr,
                                               float* __restrict__ out) {
    __shared__ __align__(16) __nv_bfloat16 As[BM][SMPAD];
    __shared__ __align__(16) __nv_bfloat16 Bs[2][64][SMPAD];
    int n0 = blockIdx.x * BM;
    int tid = threadIdx.x;
    int wid = tid >> 5, lane = tid & 31;
    int warpM = wid >> 1, warpN = wid & 1;

    float acc[2][4][4];
    #pragma unroll
    for (int mt = 0; mt < 2; mt++)
        #pragma unroll
        for (int nt = 0; nt < 4; nt++)
            #pragma unroll
            for (int q = 0; q < 4; q++) acc[mt][nt][q] = 0.f;

    const __nv_bfloat16* Bg = g_Bt2 + (size_t)l * 64 * K2B;

    // A chunks: 0=hi_agg 1=hi_rh 2=lo_agg 3=lo_rh
    // B chunks: 0=Wl5_hi 1=Wr5_hi 2=Wl5_lo 3=Wr5_lo
    // pairs: A0{B0,B2} A1{B1,B3} A2{B0} A3{B1}
    for (int kc = 0; kc < 4; kc++) {
        #pragma unroll
        for (int i = 0; i < 4; i++) {
            int idx = tid + i * 256;
            int r = idx >> 3, c8 = idx & 7;
            int4 v = make_int4(0, 0, 0, 0);
            if (n0 + r < N)
                v = *(const int4*)(g_A2 + (size_t)(n0 + r) * K2A + kc * 64 + c8 * 8);
            *(int4*)&As[r][c8 * 8] = v;
        }
        int nb = (kc < 2) ? 2 : 1;
        for (int p = 0; p < nb; p++) {
            int bk = (kc < 2) ? (kc + p * 2) : (kc - 2);
            #pragma unroll
            for (int i = 0; i < 2; i++) {
                int idx = tid + i * 256;
                int j = idx >> 3, c8 = idx & 7;
                *(int4*)&Bs[p][j][c8 * 8] =
                    *(const int4*)(Bg + (size_t)j * K2B + bk * 64 + c8 * 8);
            }
        }
        __syncthreads();
        #pragma unroll
        for (int ks = 0; ks < 4; ks++) {
            int cc = ks * 16;
            uint32_t a[2][4];
            #pragma unroll
            for (int mt = 0; mt < 2; mt++) {
                int row = warpM * 32 + mt * 16 + (lane & 15);
                int col = cc + ((lane >> 4) << 3);
                ldsm_x4(a[mt], sptr(&As[row][col]));
            }
            for (int p = 0; p < nb; p++) {
                uint32_t b[4][2];
                #pragma unroll
                for (int pr = 0; pr < 2; pr++) {
                    int j = warpN * 32 + pr * 16 + ((lane >> 4) << 3) + (lane & 7);
                    int col = cc + (((lane >> 3) & 1) << 3);
                    uint32_t t4[4];
                    ldsm_x4(t4, sptr(&Bs[p][j][col]));
                    b[pr * 2][0] = t4[0]; b[pr * 2][1] = t4[1];
                    b[pr * 2 + 1][0] = t4[2]; b[pr * 2 + 1][1] = t4[3];
                }
                #pragma unroll
                for (int mt = 0; mt < 2; mt++)
                    #pragma unroll
                    for (int nt = 0; nt < 4; nt++)
                        mma_bf16(acc[mt][nt], a[mt], b[nt]);
            }
        }
        __syncthreads();
    }

    #pragma unroll
    for (int mt = 0; mt < 2; mt++) {
        int r0 = n0 + warpM * 32 + mt * 16 + (lane >> 2);
        #pragma unroll
        for (int nt = 0; nt < 4; nt++) {
            int jc0 = warpN * 32 + nt * 8 + (lane & 3) * 2;
            #pragma unroll
            for (int q = 0; q < 4; q++) {
                int row = r0 + ((q >> 1) << 3);
                int jc  = jc0 + (q & 1);
                if (row < N) {
                    size_t o = (size_t)row * HDIM + jc;
                    float v = acc[mt][nt][q] + g_bias2[l * 64 + jc] + g_TP[o];
                    float t = tanhf(v);
                    float z = g_Z[o];
                    float hv = hptr[o];
                    out[(size_t)l * N * HDIM + o] = z * hv + (1.0f - z) * t;
                }
            }
        }
    }
}

// ---------------- launch ----------------------------------------------------
#define GEMM1_SMEM (BM * SMPAD * 2 + 2 * 192 * SMPAD * 2)   // bytes: 73728

extern "C" void kernel_launch(void* const* d_in, const int* in_sizes, int n_in,
                              void* d_out, int out_size) {
    const float* inp = (const float*)d_in[0];
    const int*   edg = (const int*)d_in[1];     // int64 in reference -> int32 in harness
    const float* h   = (const float*)d_in[2];
    const float* Wl  = (const float*)d_in[3];
    const float* b   = (const float*)d_in[4];
    const float* Wr  = (const float*)d_in[5];
    float* out = (float*)d_out;

    int N = in_sizes[0] / HDIM;
    int E = in_sizes[1] / 2;
    int L = in_sizes[2] / in_sizes[0];
    if (N > NMAX || E > EMAX || L > LMAX) return;

    cudaFuncSetAttribute(k_gemm1, cudaFuncAttributeMaxDynamicSharedMemorySize, GEMM1_SMEM);

    // CSR build
    k_zero_deg<<<(N + 255) / 256, 256>>>(N);
    k_count<<<(E + 255) / 256, 256>>>(edg, E, N);
    k_scan<<<1, 1024>>>(N);
    k_scatter<<<(E + 255) / 256, 256>>>(edg, E, N);

    // weight packing (hi/lo split, transposed + concatenated)
    k_packB1<<<(L * 192 * K1B + 255) / 256, 256>>>(Wl, Wr, L);
    k_packB2<<<(L * 64 * K2B + 255) / 256, 256>>>(Wl, Wr, L);
    k_packBias<<<(L * 256 + 255) / 256, 256>>>(b, L);

    int aggBlocks = (N * 32 + 255) / 256;
    int rowTiles  = (N + BM - 1) / BM;

    const float* x = inp;
    for (int l = 0; l < L; l++) {
        const float* hl = h + (size_t)l * N * HDIM;
        k_agg1<<<aggBlocks, 256>>>(x, hl, N);
        k_gemm1<<<rowTiles, 512, GEMM1_SMEM>>>(N, l, hl);
        k_agg2<<<aggBlocks, 256>>>(N);
        k_gemm2<<<rowTiles, 256>>>(N, l, hl, out);
        x = out + (size_t)l * N * HDIM;
    }
}

// round 4
// speedup vs baseline: 1.3777x; 1.2364x over previous
#include <cuda_runtime.h>
#include <cuda_bf16.h>
#include <cstdint>
#include <math.h>

#define NMAX 100000
#define EMAX 1600000
#define HDIM 64
#define LMAX 2
#define K1B 512   // B1 row: [hi(4x64) | lo(4x64)]
#define K2B 256   // B2 row: [hi(2x64) | lo(2x64)]

// ---------------- scratch (static device memory) ---------------------------
__device__ __align__(16) int   g_deg[NMAX];
__device__ __align__(16) int   g_rowptr[NMAX + 1];
__device__ __align__(16) int   g_cursor[NMAX];
__device__ __align__(16) int   g_csr[EMAX];
__device__ __align__(16) float g_invdeg[NMAX];
__device__ __align__(16) int   g_bsum[512];

__device__ __align__(16) float g_AGX[(size_t)NMAX * HDIM];  // mean-agg of x
__device__ __align__(16) float g_AGH[(size_t)NMAX * HDIM];  // mean-agg of h
__device__ __align__(16) float g_AG2[(size_t)NMAX * HDIM];  // mean-agg of r*h
__device__ __align__(16) float g_Z [(size_t)NMAX * HDIM];
__device__ __align__(16) float g_TP[(size_t)NMAX * HDIM];
__device__ __align__(16) float g_RH[(size_t)NMAX * HDIM];

__device__ __align__(16) __nv_bfloat16 g_Bt1[(size_t)LMAX * 192 * K1B];
__device__ __align__(16) __nv_bfloat16 g_Bt2[(size_t)LMAX * 64 * K2B];
__device__ __align__(16) float g_bias1[LMAX * 192];
__device__ __align__(16) float g_bias2[LMAX * 64];

// ---------------- helpers --------------------------------------------------
__device__ __forceinline__ float sigm(float x) { return 1.0f / (1.0f + __expf(-x)); }
__device__ __forceinline__ float fast_tanh(float x) {
    float xc = fminf(fmaxf(x, -30.0f), 30.0f);
    return 1.0f - __fdividef(2.0f, __expf(2.0f * xc) + 1.0f);
}

__device__ __forceinline__ void mma_bf16(float (&d)[4], const uint32_t (&a)[4],
                                         const uint32_t (&b)[2]) {
    asm volatile(
        "mma.sync.aligned.m16n8k16.row.col.f32.bf16.bf16.f32 "
        "{%0,%1,%2,%3}, {%4,%5,%6,%7}, {%8,%9}, {%0,%1,%2,%3};\n"
        : "+f"(d[0]), "+f"(d[1]), "+f"(d[2]), "+f"(d[3])
        : "r"(a[0]), "r"(a[1]), "r"(a[2]), "r"(a[3]), "r"(b[0]), "r"(b[1]));
}
__device__ __forceinline__ uint32_t sptr(const void* p) {
    return (uint32_t)__cvta_generic_to_shared(p);
}
__device__ __forceinline__ void ldsm_x4(uint32_t (&r)[4], uint32_t addr) {
    asm volatile("ldmatrix.sync.aligned.m8n8.x4.shared.b16 {%0,%1,%2,%3}, [%4];\n"
                 : "=r"(r[0]), "=r"(r[1]), "=r"(r[2]), "=r"(r[3]) : "r"(addr));
}
// pack two floats: hi pair and lo pair (bf16x2)
__device__ __forceinline__ void split_pack2(float a, float b, uint32_t& hi2, uint32_t& lo2) {
    __nv_bfloat16 ha = __float2bfloat16_rn(a), hb = __float2bfloat16_rn(b);
    __nv_bfloat16 la = __float2bfloat16_rn(a - __bfloat162float(ha));
    __nv_bfloat16 lb = __float2bfloat16_rn(b - __bfloat162float(hb));
    hi2 = ((uint32_t)__bfloat16_as_ushort(hb) << 16) | __bfloat16_as_ushort(ha);
    lo2 = ((uint32_t)__bfloat16_as_ushort(lb) << 16) | __bfloat16_as_ushort(la);
}

// ---------------- CSR build ------------------------------------------------
__global__ void k_zero_deg(int N) {
    int i = blockIdx.x * blockDim.x + threadIdx.x;
    if (i < N) g_deg[i] = 0;
}

__global__ void k_count(const int* __restrict__ edg, int E, int N) {
    int e = blockIdx.x * blockDim.x + threadIdx.x;
    if (e < E) {
        int dst = edg[E + e];
        if ((unsigned)dst < (unsigned)N) atomicAdd(&g_deg[dst], 1);
    }
}

// parallel 3-phase scan
__global__ void k_scan1(int N) {
    __shared__ int ws[8];
    int tid = threadIdx.x, lane = tid & 31, wid = tid >> 5;
    int i = blockIdx.x * 256 + tid;
    int v = (i < N) ? g_deg[i] : 0;
    int x = v;
    #pragma unroll
    for (int o = 1; o < 32; o <<= 1) x += __shfl_down_sync(0xffffffffu, x, o);
    if (lane == 0) ws[wid] = x;
    __syncthreads();
    if (tid == 0) {
        int s = 0;
        #pragma unroll
        for (int w = 0; w < 8; w++) s += ws[w];
        g_bsum[blockIdx.x] = s;
    }
}

__global__ void k_scan2(int nb, int N) {
    // single block, nb <= 512
    __shared__ int ws[16];
    int tid = threadIdx.x, lane = tid & 31, wid = tid >> 5;
    int v = (tid < nb) ? g_bsum[tid] : 0;
    int x = v;
    #pragma unroll
    for (int o = 1; o < 32; o <<= 1) {
        int y = __shfl_up_sync(0xffffffffu, x, o);
        if (lane >= o) x += y;
    }
    if (lane == 31) ws[wid] = x;
    __syncthreads();
    if (wid == 0 && lane < 16) {
        int w = ws[lane];
        #pragma unroll
        for (int o = 1; o < 16; o <<= 1) {
            int y = __shfl_up_sync(0xffffu, w, o);
            if (lane >= o) w += y;
        }
        ws[lane] = w;
    }
    __syncthreads();
    int excl = x - v + (wid > 0 ? ws[wid - 1] : 0);
    if (tid < nb) g_bsum[tid] = excl;
    if (tid == nb - 1) g_rowptr[N] = excl + v;
}

__global__ void k_scan3(int N) {
    __shared__ int ws[8];
    int tid = threadIdx.x, lane = tid & 31, wid = tid >> 5;
    int i = blockIdx.x * 256 + tid;
    int v = (i < N) ? g_deg[i] : 0;
    int x = v;
    #pragma unroll
    for (int o = 1; o < 32; o <<= 1) {
        int y = __shfl_up_sync(0xffffffffu, x, o);
        if (lane >= o) x += y;
    }
    if (lane == 31) ws[wid] = x;
    __syncthreads();
    if (wid == 0 && lane < 8) {
        int w = ws[lane];
        #pragma unroll
        for (int o = 1; o < 8; o <<= 1) {
            int y = __shfl_up_sync(0xffu, w, o);
            if (lane >= o) w += y;
        }
        ws[lane] = w;
    }
    __syncthreads();
    if (i < N) {
        int excl = x - v + (wid > 0 ? ws[wid - 1] : 0) + g_bsum[blockIdx.x];
        g_rowptr[i] = excl;
        g_cursor[i] = excl;
        g_invdeg[i] = (v > 0) ? 1.0f / (float)v : 0.0f;
    }
}

__global__ void k_scatter(const int* __restrict__ edg, int E, int N) {
    int e = blockIdx.x * blockDim.x + threadIdx.x;
    if (e < E) {
        int src = edg[e];
        int dst = edg[E + e];
        if ((unsigned)src < (unsigned)N && (unsigned)dst < (unsigned)N) {
            int pos = atomicAdd(&g_cursor[dst], 1);
            g_csr[pos] = src;
        }
    }
}

// ---------------- weight / bias packing ------------------------------------
// B1[l][j][k]: j = g*64+jj (g: 0=z 1=r 2=t-partial), k = t*256 + s*64 + c
// s: 0=Wl(g0) 1=Wr(g0) 2=Wl(g1) 3=Wr(g1); gate pairs (0,1),(2,3),(4,-); t: 0=hi 1=lo
__global__ void k_packB1(const float* __restrict__ Wl, const float* __restrict__ Wr, int L) {
    int idx = blockIdx.x * blockDim.x + threadIdx.x;
    int total = L * 192 * K1B;
    if (idx >= total) return;
    int k = idx % K1B;
    int j = (idx / K1B) % 192;
    int l = idx / (K1B * 192);
    int t = k / 256, rem = k % 256, s = rem / 64, c = rem % 64;
    int g = j / 64, jj = j % 64;
    int gbase = 2 * g;
    float w = 0.0f;
    if (s == 0)      w = Wl[(((size_t)l * 6 + gbase) * 64 + jj) * 64 + c];
    else if (s == 1) w = Wr[(((size_t)l * 6 + gbase) * 64 + jj) * 64 + c];
    else if (s == 2) { if (g < 2) w = Wl[(((size_t)l * 6 + gbase + 1) * 64 + jj) * 64 + c]; }
    else             { if (g < 2) w = Wr[(((size_t)l * 6 + gbase + 1) * 64 + jj) * 64 + c]; }
    __nv_bfloat16 hi = __float2bfloat16_rn(w);
    __nv_bfloat16 val = (t == 1) ? __float2bfloat16_rn(w - __bfloat162float(hi)) : hi;
    g_Bt1[(size_t)(l * 192 + j) * K1B + k] = val;
}

// B2[l][j][k]: k = t*128 + s*64 + c ; s: 0=Wl5(agg_rh) 1=Wr5(rh); t: 0=hi 1=lo
__global__ void k_packB2(const float* __restrict__ Wl, const float* __restrict__ Wr, int L) {
    int idx = blockIdx.x * blockDim.x + threadIdx.x;
    int total = L * 64 * K2B;
    if (idx >= total) return;
    int k = idx % K2B;
    int j = (idx / K2B) % 64;
    int l = idx / (K2B * 64);
    int t = k / 128, rem = k % 128, s = rem / 64, c = rem % 64;
    const float* W = s ? Wr : Wl;
    float w = W[(((size_t)l * 6 + 5) * 64 + j) * 64 + c];
    __nv_bfloat16 hi = __float2bfloat16_rn(w);
    __nv_bfloat16 val = (t == 1) ? __float2bfloat16_rn(w - __bfloat162float(hi)) : hi;
    g_Bt2[(size_t)(l * 64 + j) * K2B + k] = val;
}

__global__ void k_packBias(const float* __restrict__ b, int L) {
    int idx = blockIdx.x * blockDim.x + threadIdx.x;
    int total = L * 256;
    if (idx >= total) return;
    int j = idx % 256, l = idx / 256;
    if (j < 192) {
        int g = j / 64, jj = j % 64;
        float v;
        if (g == 0)      v = b[((size_t)l * 6 + 0) * 64 + jj] + b[((size_t)l * 6 + 1) * 64 + jj];
        else if (g == 1) v = b[((size_t)l * 6 + 2) * 64 + jj] + b[((size_t)l * 6 + 3) * 64 + jj];
        else             v = b[((size_t)l * 6 + 4) * 64 + jj];
        g_bias1[l * 192 + j] = v;
    } else {
        int jj = j - 192;
        g_bias2[l * 64 + jj] = b[((size_t)l * 6 + 5) * 64 + jj];
    }
}

// ---------------- aggregation (warp per node, CSR gather, f32 out) ---------
__global__ void k_agg1(const float* __restrict__ x, const float* __restrict__ h, int N) {
    int warp = (blockIdx.x * blockDim.x + threadIdx.x) >> 5;
    if (warp >= N) return;
    int lane = threadIdx.x & 31;
    int beg = g_rowptr[warp], end = g_rowptr[warp + 1];
    float sx0 = 0.f, sx1 = 0.f, sh0 = 0.f, sh1 = 0.f;
    int e = beg;
    for (; e + 1 < end; e += 2) {
        int s0 = g_csr[e], s1 = g_csr[e + 1];
        const float* xr0 = x + (size_t)s0 * HDIM;
        const float* hr0 = h + (size_t)s0 * HDIM;
        const float* xr1 = x + (size_t)s1 * HDIM;
        const float* hr1 = h + (size_t)s1 * HDIM;
        sx0 += xr0[lane] + xr1[lane];
        sx1 += xr0[lane + 32] + xr1[lane + 32];
        sh0 += hr0[lane] + hr1[lane];
        sh1 += hr0[lane + 32] + hr1[lane + 32];
    }
    if (e < end) {
        int s = g_csr[e];
        const float* xr = x + (size_t)s * HDIM;
        const float* hr = h + (size_t)s * HDIM;
        sx0 += xr[lane];  sx1 += xr[lane + 32];
        sh0 += hr[lane];  sh1 += hr[lane + 32];
    }
    float inv = g_invdeg[warp];
    size_t o = (size_t)warp * HDIM;
    g_AGX[o + lane] = sx0 * inv;  g_AGX[o + lane + 32] = sx1 * inv;
    g_AGH[o + lane] = sh0 * inv;  g_AGH[o + lane + 32] = sh1 * inv;
}

__global__ void k_agg2(int N) {
    int warp = (blockIdx.x * blockDim.x + threadIdx.x) >> 5;
    if (warp >= N) return;
    int lane = threadIdx.x & 31;
    int beg = g_rowptr[warp], end = g_rowptr[warp + 1];
    float s0 = 0.f, s1 = 0.f;
    int e = beg;
    for (; e + 1 < end; e += 2) {
        const float* r0 = g_RH + (size_t)g_csr[e] * HDIM;
        const float* r1 = g_RH + (size_t)g_csr[e + 1] * HDIM;
        s0 += r0[lane] + r1[lane];
        s1 += r0[lane + 32] + r1[lane + 32];
    }
    if (e < end) {
        const float* rr = g_RH + (size_t)g_csr[e] * HDIM;
        s0 += rr[lane];
        s1 += rr[lane + 32];
    }
    float inv = g_invdeg[warp];
    size_t o = (size_t)warp * HDIM;
    g_AG2[o + lane] = s0 * inv;
    g_AG2[o + lane + 32] = s1 * inv;
}

// ---------------- GEMM 1: all gates fused, f32 sources, inline split -------
// 512 threads, 16 warps (4M x 4N), BM=128, BN=192, warp tile 32x48
#define BM 128
#define SMPAD 72
// dynamic smem layout (bf16 elements): AsHi[128*72] AsLo[128*72] BsHi[192*72] BsLo[192*72]
#define G1_ASHI 0
#define G1_ASLO (128 * SMPAD)
#define G1_BSHI (2 * 128 * SMPAD)
#define G1_BSLO (2 * 128 * SMPAD + 192 * SMPAD)
#define GEMM1_SMEM ((2 * 128 * SMPAD + 2 * 192 * SMPAD) * 2)

__global__ void __launch_bounds__(512) k_gemm1(int N, int l,
                                               const float* __restrict__ xptr,
                                               const float* __restrict__ hptr) {
    extern __shared__ __nv_bfloat16 sm[];
    __nv_bfloat16* AsHi = sm + G1_ASHI;
    __nv_bfloat16* AsLo = sm + G1_ASLO;
    __nv_bfloat16* BsHi = sm + G1_BSHI;
    __nv_bfloat16* BsLo = sm + G1_BSLO;

    int n0 = blockIdx.x * BM;
    int tid = threadIdx.x;
    int wid = tid >> 5, lane = tid & 31;
    int warpM = wid >> 2, warpN = wid & 3;

    float acc[2][6][4];
    #pragma unroll
    for (int mt = 0; mt < 2; mt++)
        #pragma unroll
        for (int nt = 0; nt < 6; nt++)
            #pragma unroll
            for (int q = 0; q < 4; q++) acc[mt][nt][q] = 0.f;

    const __nv_bfloat16* Bg = g_Bt1 + (size_t)l * 192 * K1B;

    #pragma unroll 1
    for (int s = 0; s < 4; s++) {
        const float* S = (s == 0) ? g_AGX : (s == 1) ? xptr : (s == 2) ? g_AGH : hptr;
        // A fill: 128x64 f32 -> hi/lo bf16; 2048 float4 units / 512 threads
        #pragma unroll
        for (int i = 0; i < 4; i++) {
            int idx = tid + i * 512;
            int r = idx >> 4, q4 = idx & 15;
            float4 v = make_float4(0.f, 0.f, 0.f, 0.f);
            if (n0 + r < N)
                v = *(const float4*)(S + (size_t)(n0 + r) * HDIM + q4 * 4);
            uint32_t h0, l0, h1, l1;
            split_pack2(v.x, v.y, h0, l0);
            split_pack2(v.z, v.w, h1, l1);
            uint2 hv = make_uint2(h0, h1), lv = make_uint2(l0, l1);
            *(uint2*)(AsHi + r * SMPAD + q4 * 4) = hv;
            *(uint2*)(AsLo + r * SMPAD + q4 * 4) = lv;
        }
        // B fill: 192x64 hi + 192x64 lo; 1536 int4 units each / 512 threads
        #pragma unroll
        for (int i = 0; i < 3; i++) {
            int idx = tid + i * 512;
            int j = idx >> 3, c8 = idx & 7;
            *(int4*)(BsHi + j * SMPAD + c8 * 8) =
                *(const int4*)(Bg + (size_t)j * K1B + s * 64 + c8 * 8);
            *(int4*)(BsLo + j * SMPAD + c8 * 8) =
                *(const int4*)(Bg + (size_t)j * K1B + 256 + s * 64 + c8 * 8);
        }
        __syncthreads();
        #pragma unroll
        for (int ks = 0; ks < 4; ks++) {
            int cc = ks * 16;
            uint32_t ah[2][4], al[2][4];
            #pragma unroll
            for (int mt = 0; mt < 2; mt++) {
                int row = warpM * 32 + mt * 16 + (lane & 15);
                int col = cc + ((lane >> 4) << 3);
                ldsm_x4(ah[mt], sptr(AsHi + row * SMPAD + col));
                ldsm_x4(al[mt], sptr(AsLo + row * SMPAD + col));
            }
            uint32_t bh[6][2], bl[6][2];
            #pragma unroll
            for (int pr = 0; pr < 3; pr++) {
                int j = warpN * 48 + pr * 16 + ((lane >> 4) << 3) + (lane & 7);
                int col = cc + (((lane >> 3) & 1) << 3);
                uint32_t t4[4];
                ldsm_x4(t4, sptr(BsHi + j * SMPAD + col));
                bh[pr * 2][0] = t4[0]; bh[pr * 2][1] = t4[1];
                bh[pr * 2 + 1][0] = t4[2]; bh[pr * 2 + 1][1] = t4[3];
                ldsm_x4(t4, sptr(BsLo + j * SMPAD + col));
                bl[pr * 2][0] = t4[0]; bl[pr * 2][1] = t4[1];
                bl[pr * 2 + 1][0] = t4[2]; bl[pr * 2 + 1][1] = t4[3];
            }
            #pragma unroll
            for (int mt = 0; mt < 2; mt++)
                #pragma unroll
                for (int nt = 0; nt < 6; nt++) {
                    mma_bf16(acc[mt][nt], ah[mt], bh[nt]);
                    mma_bf16(acc[mt][nt], ah[mt], bl[nt]);
                    mma_bf16(acc[mt][nt], al[mt], bh[nt]);
                }
        }
        __syncthreads();
    }

    // fused epilogue: z | r -> rh | t-partial
    #pragma unroll
    for (int mt = 0; mt < 2; mt++) {
        int r0 = n0 + warpM * 32 + mt * 16 + (lane >> 2);
        #pragma unroll
        for (int nt = 0; nt < 6; nt++) {
            int jc0 = warpN * 48 + nt * 8 + (lane & 3) * 2;
            #pragma unroll
            for (int q = 0; q < 4; q++) {
                int row = r0 + ((q >> 1) << 3);
                int jc  = jc0 + (q & 1);
                if (row < N) {
                    float v = acc[mt][nt][q] + g_bias1[l * 192 + jc];
                    int jj = jc & 63;
                    size_t o = (size_t)row * HDIM + jj;
                    if (jc < 64) {
                        g_Z[o] = sigm(v);
                    } else if (jc < 128) {
                        float r = sigm(v);
                        g_RH[o] = r * hptr[o];
                    } else {
                        g_TP[o] = v;
                    }
                }
            }
        }
    }
}

// ---------------- GEMM 2: gate 5 + final GRU combine -----------------------
// 256 threads, 8 warps (4M x 2N), BM=128, BN=64, warp tile 32x32
#define G2_ASHI 0
#define G2_ASLO (128 * SMPAD)
#define G2_BSHI (2 * 128 * SMPAD)
#define G2_BSLO (2 * 128 * SMPAD + 64 * SMPAD)
#define GEMM2_SMEM ((2 * 128 * SMPAD + 2 * 64 * SMPAD) * 2)

__global__ void __launch_bounds__(256) k_gemm2(int N, int l,
                                               const float* __restrict__ hptr,
                                               float* __restrict__ out) {
    extern __shared__ __nv_bfloat16 sm[];
    __nv_bfloat16* AsHi = sm + G2_ASHI;
    __nv_bfloat16* AsLo = sm + G2_ASLO;
    __nv_bfloat16* BsHi = sm + G2_BSHI;
    __nv_bfloat16* BsLo = sm + G2_BSLO;

    int n0 = blockIdx.x * BM;
    int tid = threadIdx.x;
    int wid = tid >> 5, lane = tid & 31;
    int warpM = wid >> 1, warpN = wid & 1;

    float acc[2][4][4];
    #pragma unroll
    for (int mt = 0; mt < 2; mt++)
        #pragma unroll
        for (int nt = 0; nt < 4; nt++)
            #pragma unroll
            for (int q = 0; q < 4; q++) acc[mt][nt][q] = 0.f;

    const __nv_bfloat16* Bg = g_Bt2 + (size_t)l * 64 * K2B;

    #pragma unroll 1
    for (int s = 0; s < 2; s++) {
        const float* S = (s == 0) ? g_AG2 : g_RH;
        #pragma unroll
        for (int i = 0; i < 8; i++) {
            int idx = tid + i * 256;
            int r = idx >> 4, q4 = idx & 15;
            float4 v = make_float4(0.f, 0.f, 0.f, 0.f);
            if (n0 + r < N)
                v = *(const float4*)(S + (size_t)(n0 + r) * HDIM + q4 * 4);
            uint32_t h0, l0, h1, l1;
            split_pack2(v.x, v.y, h0, l0);
            split_pack2(v.z, v.w, h1, l1);
            *(uint2*)(AsHi + r * SMPAD + q4 * 4) = make_uint2(h0, h1);
            *(uint2*)(AsLo + r * SMPAD + q4 * 4) = make_uint2(l0, l1);
        }
        #pragma unroll
        for (int i = 0; i < 2; i++) {
            int idx = tid + i * 256;
            int j = idx >> 3, c8 = idx & 7;
            *(int4*)(BsHi + j * SMPAD + c8 * 8) =
                *(const int4*)(Bg + (size_t)j * K2B + s * 64 + c8 * 8);
            *(int4*)(BsLo + j * SMPAD + c8 * 8) =
                *(const int4*)(Bg + (size_t)j * K2B + 128 + s * 64 + c8 * 8);
        }
        __syncthreads();
        #pragma unroll
        for (int ks = 0; ks < 4; ks++) {
            int cc = ks * 16;
            uint32_t ah[2][4], al[2][4];
            #pragma unroll
            for (int mt = 0; mt < 2; mt++) {
                int row = warpM * 32 + mt * 16 + (lane & 15);
                int col = cc + ((lane >> 4) << 3);
                ldsm_x4(ah[mt], sptr(AsHi + row * SMPAD + col));
                ldsm_x4(al[mt], sptr(AsLo + row * SMPAD + col));
            }
            uint32_t bh[4][2], bl[4][2];
            #pragma unroll
            for (int pr = 0; pr < 2; pr++) {
                int j = warpN * 32 + pr * 16 + ((lane >> 4) << 3) + (lane & 7);
                int col = cc + (((lane >> 3) & 1) << 3);
                uint32_t t4[4];
                ldsm_x4(t4, sptr(BsHi + j * SMPAD + col));
                bh[pr * 2][0] = t4[0]; bh[pr * 2][1] = t4[1];
                bh[pr * 2 + 1][0] = t4[2]; bh[pr * 2 + 1][1] = t4[3];
                ldsm_x4(t4, sptr(BsLo + j * SMPAD + col));
                bl[pr * 2][0] = t4[0]; bl[pr * 2][1] = t4[1];
                bl[pr * 2 + 1][0] = t4[2]; bl[pr * 2 + 1][1] = t4[3];
            }
            #pragma unroll
            for (int mt = 0; mt < 2; mt++)
                #pragma unroll
                for (int nt = 0; nt < 4; nt++) {
                    mma_bf16(acc[mt][nt], ah[mt], bh[nt]);
                    mma_bf16(acc[mt][nt], ah[mt], bl[nt]);
                    mma_bf16(acc[mt][nt], al[mt], bh[nt]);
                }
        }
        __syncthreads();
    }

    #pragma unroll
    for (int mt = 0; mt < 2; mt++) {
        int r0 = n0 + warpM * 32 + mt * 16 + (lane >> 2);
        #pragma unroll
        for (int nt = 0; nt < 4; nt++) {
            int jc0 = warpN * 32 + nt * 8 + (lane & 3) * 2;
            #pragma unroll
            for (int q = 0; q < 4; q++) {
                int row = r0 + ((q >> 1) << 3);
                int jc  = jc0 + (q & 1);
                if (row < N) {
                    size_t o = (size_t)row * HDIM + jc;
                    float v = acc[mt][nt][q] + g_bias2[l * 64 + jc] + g_TP[o];
                    float t = fast_tanh(v);
                    float z = g_Z[o];
                    float hv = hptr[o];
                    out[(size_t)l * N * HDIM + o] = z * hv + (1.0f - z) * t;
                }
            }
        }
    }
}

// ---------------- launch ----------------------------------------------------
extern "C" void kernel_launch(void* const* d_in, const int* in_sizes, int n_in,
                              void* d_out, int out_size) {
    const float* inp = (const float*)d_in[0];
    const int*   edg = (const int*)d_in[1];   // int64 in reference -> int32 in harness
    const float* h   = (const float*)d_in[2];
    const float* Wl  = (const float*)d_in[3];
    const float* b   = (const float*)d_in[4];
    const float* Wr  = (const float*)d_in[5];
    float* out = (float*)d_out;

    int N = in_sizes[0] / HDIM;
    int E = in_sizes[1] / 2;
    int L = in_sizes[2] / in_sizes[0];
    if (N > NMAX || E > EMAX || L > LMAX) return;

    cudaFuncSetAttribute(k_gemm1, cudaFuncAttributeMaxDynamicSharedMemorySize, GEMM1_SMEM);
    cudaFuncSetAttribute(k_gemm2, cudaFuncAttributeMaxDynamicSharedMemorySize, GEMM2_SMEM);

    int scanBlocks = (N + 255) / 256;   // <= 391 for NMAX

    // CSR build
    k_zero_deg<<<(N + 255) / 256, 256>>>(N);
    k_count<<<(E + 255) / 256, 256>>>(edg, E, N);
    k_scan1<<<scanBlocks, 256>>>(N);
    k_scan2<<<1, 512>>>(scanBlocks, N);
    k_scan3<<<scanBlocks, 256>>>(N);
    k_scatter<<<(E + 255) / 256, 256>>>(edg, E, N);

    // weight packing
    k_packB1<<<(L * 192 * K1B + 255) / 256, 256>>>(Wl, Wr, L);
    k_packB2<<<(L * 64 * K2B + 255) / 256, 256>>>(Wl, Wr, L);
    k_packBias<<<(L * 256 + 255) / 256, 256>>>(b, L);

    int aggBlocks = (N * 32 + 255) / 256;
    int rowTiles  = (N + BM - 1) / BM;

    const float* x = inp;
    for (int l = 0; l < L; l++) {
        const float* hl = h + (size_t)l * N * HDIM;
        k_agg1<<<aggBlocks, 256>>>(x, hl, N);
        k_gemm1<<<rowTiles, 512, GEMM1_SMEM>>>(N, l, x, hl);
        k_agg2<<<aggBlocks, 256>>>(N);
        k_gemm2<<<rowTiles, 256, GEMM2_SMEM>>>(N, l, hl, out);
        x = out + (size_t)l * N * HDIM;
    }
}